// round 6
// baseline (speedup 1.0000x reference)
#include <cuda_runtime.h>
#include <cuda_bf16.h>
#include <cstdint>

// ---------------------------------------------------------------------------
// HeteroEdgePromptPlus — folded formulation.
//   logits[e,k] = srcLogits[src(e),k] + dstLogits[dst(e),k]   (bias folded)
//   b = softmax(leaky_relu(logits)) ; out[e] = b @ A
// Edge phase split: softmax_kernel writes b[e,16]; outmm_kernel does b @ A.
// ---------------------------------------------------------------------------

#define MAXN 50000
#define MAXE 800000
typedef unsigned long long ull;

__device__ float g_Mp[48 * 256];
__device__ float g_cp[48];
__device__ float g_Ma[16 * 128];
__device__ float g_ca[16];
__device__ float g_paperL[(size_t)MAXN * 48];
__device__ float g_authorL[(size_t)MAXN * 16];
__device__ float g_b[(size_t)2 * MAXE * 16];   // softmax weights scratch

// ---- f32x2 packed helpers (Blackwell) -------------------------------------
__device__ __forceinline__ ull pk2(float x, float y) {
    ull r;
    asm("mov.b64 %0, {%1, %2};" : "=l"(r) : "f"(x), "f"(y));
    return r;
}
__device__ __forceinline__ void upk(ull v, float& x, float& y) {
    asm("mov.b64 {%0, %1}, %2;" : "=f"(x), "=f"(y) : "l"(v));
}
__device__ __forceinline__ void fma2(ull& d, ull a, ull b) {
    asm("fma.rn.f32x2 %0, %1, %2, %0;" : "+l"(d) : "l"(a), "l"(b));
}

// ---------------------------------------------------------------------------
// Kernel 1: fold weights. grid = (64, 4): x = output row, y = p-chunk of 32.
// Accumulate partial dot products with atomicAdd (g_* memset to 0 first).
// ---------------------------------------------------------------------------
__global__ void fold_kernel(const float* __restrict__ Wp_p,
                            const float* __restrict__ bp_p,
                            const float* __restrict__ Wp_a,
                            const float* __restrict__ bp_a,
                            const float* __restrict__ Ws_w,
                            const float* __restrict__ bs_w,
                            const float* __restrict__ Ws_c,
                            const float* __restrict__ bs_c) {
    const int b = blockIdx.x, t = threadIdx.x;
    const int pBeg = blockIdx.y * 32, pEnd = pBeg + 32;
    if (b < 48) {
        int k = b & 15, grp = b >> 4;
        const float* wrow = (grp == 0) ? (Ws_w + k * 256 + 128)
                          : (grp == 1) ? (Ws_c + k * 256)
                                       : (Ws_c + k * 256 + 128);
        float a0 = 0.f, a1 = 0.f, a2 = 0.f, a3 = 0.f;
        #pragma unroll
        for (int p = pBeg; p < pEnd; p += 4) {
            a0 = fmaf(__ldg(&wrow[p + 0]), __ldg(&Wp_p[(p + 0) * 256 + t]), a0);
            a1 = fmaf(__ldg(&wrow[p + 1]), __ldg(&Wp_p[(p + 1) * 256 + t]), a1);
            a2 = fmaf(__ldg(&wrow[p + 2]), __ldg(&Wp_p[(p + 2) * 256 + t]), a2);
            a3 = fmaf(__ldg(&wrow[p + 3]), __ldg(&Wp_p[(p + 3) * 256 + t]), a3);
        }
        atomicAdd(&g_Mp[b * 256 + t], (a0 + a1) + (a2 + a3));
        if (t == 0) {
            float c0 = (blockIdx.y == 0)
                           ? ((grp == 0) ? bs_w[k] : (grp == 2) ? bs_c[k] : 0.f)
                           : 0.f;
            float c1 = 0.f, c2 = 0.f, c3 = 0.f;
            #pragma unroll
            for (int p = pBeg; p < pEnd; p += 4) {
                c0 = fmaf(wrow[p + 0], bp_p[p + 0], c0);
                c1 = fmaf(wrow[p + 1], bp_p[p + 1], c1);
                c2 = fmaf(wrow[p + 2], bp_p[p + 2], c2);
                c3 = fmaf(wrow[p + 3], bp_p[p + 3], c3);
            }
            atomicAdd(&g_cp[b], (c0 + c1) + (c2 + c3));
        }
    } else {
        int k = b - 48;
        if (t < 128) {
            const float* wrow = Ws_w + k * 256;  // src half -> author
            float a0 = 0.f, a1 = 0.f, a2 = 0.f, a3 = 0.f;
            #pragma unroll
            for (int p = pBeg; p < pEnd; p += 4) {
                a0 = fmaf(__ldg(&wrow[p + 0]), __ldg(&Wp_a[(p + 0) * 128 + t]), a0);
                a1 = fmaf(__ldg(&wrow[p + 1]), __ldg(&Wp_a[(p + 1) * 128 + t]), a1);
                a2 = fmaf(__ldg(&wrow[p + 2]), __ldg(&Wp_a[(p + 2) * 128 + t]), a2);
                a3 = fmaf(__ldg(&wrow[p + 3]), __ldg(&Wp_a[(p + 3) * 128 + t]), a3);
            }
            atomicAdd(&g_Ma[k * 128 + t], (a0 + a1) + (a2 + a3));
            if (t == 0) {
                float c0 = 0.f, c1 = 0.f, c2 = 0.f, c3 = 0.f;
                #pragma unroll
                for (int p = pBeg; p < pEnd; p += 4) {
                    c0 = fmaf(wrow[p + 0], bp_a[p + 0], c0);
                    c1 = fmaf(wrow[p + 1], bp_a[p + 1], c1);
                    c2 = fmaf(wrow[p + 2], bp_a[p + 2], c2);
                    c3 = fmaf(wrow[p + 3], bp_a[p + 3], c3);
                }
                atomicAdd(&g_ca[k], (c0 + c1) + (c2 + c3));
            }
        }
    }
}

// ---------------------------------------------------------------------------
// Kernel 2: node logits  out[N,KOUT] = X[N,KDIM] @ M[KOUT,KDIM].T + c
// ---------------------------------------------------------------------------
template <int KDIM, int KOUT, int OPT>
__device__ __forceinline__ void node_body(const float* __restrict__ X,
                                          const float* __restrict__ M,
                                          const float* __restrict__ c,
                                          float* __restrict__ out, int N,
                                          int blk, float* Xs, float* Ms) {
    constexpr int KT = 32;
    const int t = threadIdx.x;
    const int n0 = blk * 128;
    const int ng = t & 63;
    const int og = t >> 6;

    ull acc0[OPT / 2], acc1[OPT / 2];
    #pragma unroll
    for (int i = 0; i < OPT / 2; i++) { acc0[i] = 0ull; acc1[i] = 0ull; }

    const int sn = n0 + (t >> 1);
    const int sj = (t & 1) * 16;
    const bool vs = sn < N;
    const float* xrow = X + (size_t)(vs ? sn : (N - 1)) * KDIM;

    for (int j0 = 0; j0 < KDIM; j0 += KT) {
        #pragma unroll
        for (int q = 0; q < 4; q++) {
            float4 v = vs ? *reinterpret_cast<const float4*>(xrow + j0 + sj + 4 * q)
                          : make_float4(0.f, 0.f, 0.f, 0.f);
            int jj = sj + 4 * q;
            Xs[(jj + 0) * 128 + (t >> 1)] = v.x;
            Xs[(jj + 1) * 128 + (t >> 1)] = v.y;
            Xs[(jj + 2) * 128 + (t >> 1)] = v.z;
            Xs[(jj + 3) * 128 + (t >> 1)] = v.w;
        }
        #pragma unroll
        for (int idx = t; idx < KT * KOUT; idx += 256) {
            int j = idx / KOUT, k = idx - j * KOUT;
            Ms[j * KOUT + k] = M[k * KDIM + j0 + j];
        }
        __syncthreads();
        #pragma unroll
        for (int j = 0; j < KT; j++) {
            float2 xv = *reinterpret_cast<const float2*>(&Xs[j * 128 + 2 * ng]);
            ull xx = pk2(xv.x, xv.x);
            ull yy = pk2(xv.y, xv.y);
            #pragma unroll
            for (int cp = 0; cp < OPT / 2; cp++) {
                ull m2 = *reinterpret_cast<const ull*>(&Ms[j * KOUT + og * OPT + 2 * cp]);
                fma2(acc0[cp], xx, m2);
                fma2(acc1[cp], yy, m2);
            }
        }
        __syncthreads();
    }

    float r0[OPT], r1[OPT];
    #pragma unroll
    for (int cp = 0; cp < OPT / 2; cp++) {
        upk(acc0[cp], r0[2 * cp], r0[2 * cp + 1]);
        upk(acc1[cp], r1[2 * cp], r1[2 * cp + 1]);
    }
    #pragma unroll
    for (int cc = 0; cc < OPT; cc++) {
        float bias = __ldg(&c[og * OPT + cc]);
        r0[cc] += bias;
        r1[cc] += bias;
    }
    const int nA = n0 + 2 * ng, nB = nA + 1;
    if (nA < N) {
        #pragma unroll
        for (int v = 0; v < OPT / 4; v++)
            *reinterpret_cast<float4*>(&out[(size_t)nA * KOUT + og * OPT + 4 * v]) =
                make_float4(r0[4 * v], r0[4 * v + 1], r0[4 * v + 2], r0[4 * v + 3]);
    }
    if (nB < N) {
        #pragma unroll
        for (int v = 0; v < OPT / 4; v++)
            *reinterpret_cast<float4*>(&out[(size_t)nB * KOUT + og * OPT + 4 * v]) =
                make_float4(r1[4 * v], r1[4 * v + 1], r1[4 * v + 2], r1[4 * v + 3]);
    }
}

__global__ void __launch_bounds__(256)
node_kernel(const float* __restrict__ xp, const float* __restrict__ xa,
            const float* __restrict__ Mp, const float* __restrict__ cp,
            const float* __restrict__ Ma, const float* __restrict__ ca,
            float* __restrict__ pL, float* __restrict__ aL,
            int Np, int Na, int npBlocks) {
    __shared__ float Xs[32 * 128];
    __shared__ float Ms[32 * 48];
    if ((int)blockIdx.x < npBlocks)
        node_body<256, 48, 12>(xp, Mp, cp, pL, Np, blockIdx.x, Xs, Ms);
    else
        node_body<128, 16, 4>(xa, Ma, ca, aL, Na, blockIdx.x - npBlocks, Xs, Ms);
}

// ---------------------------------------------------------------------------
// Kernel 3a: gather + softmax -> b table. Half-warp per edge, 8 edges/warp/it
// (deep gather MLP). Tiny register state -> high occupancy hides latency.
// ---------------------------------------------------------------------------
__global__ void __launch_bounds__(256)
softmax_kernel(const int* __restrict__ eiW, const int* __restrict__ eiC, int E,
               const float* __restrict__ aL, const float* __restrict__ pL,
               float* __restrict__ bBase, int nbHalf) {
    const bool isW = (int)blockIdx.x < nbHalf;
    const int bid = isW ? blockIdx.x : blockIdx.x - nbHalf;
    const int* ei = isW ? eiW : eiC;
    const float* srcL = isW ? aL : (pL + 16);
    const int sStride = isW ? 16 : 48;
    const float* dstL = isW ? pL : (pL + 32);
    float* bOut = bBase + (isW ? 0 : (size_t)E * 16);

    const int lane = threadIdx.x & 31;
    const int w = threadIdx.x >> 5;
    const int k16 = lane & 15;
    const int half = lane >> 4;

    const int gw = bid * 8 + w;
    const int stepE = nbHalf * 8 * 8;

    for (int e0 = gw * 8; e0 < E; e0 += stepE) {
        float ex[4], sm[4];
        #pragma unroll
        for (int u = 0; u < 4; u++) {
            int e = min(e0 + 2 * u + half, E - 1);
            int s = __ldg(&ei[e]);
            int d = __ldg(&ei[E + e]);
            float lg = __ldg(&srcL[(size_t)s * sStride + k16]) +
                       __ldg(&dstL[(size_t)d * 48 + k16]);
            lg = fmaxf(lg, 0.01f * lg);  // leaky_relu
            // no max-subtraction: logits bounded, fp32 headroom is huge
            ex[u] = __expf(lg);
            sm[u] = ex[u];
        }
        #pragma unroll
        for (int m = 8; m; m >>= 1) {
            #pragma unroll
            for (int u = 0; u < 4; u++)
                sm[u] += __shfl_xor_sync(0xffffffffu, sm[u], m, 16);
        }
        #pragma unroll
        for (int u = 0; u < 4; u++) {
            int e = e0 + 2 * u + half;
            if (e < E)
                bOut[(size_t)(e0 + 2 * u) * 16 + lane] = __fdividef(ex[u], sm[u]);
        }
    }
}

// ---------------------------------------------------------------------------
// Kernel 3b: out[e,128] = b[e,16] @ A[16,128]. Column-half warp pairs:
// warp owns 64 cols (lane owns 2) -> A = 16 ull regs (32 regs). ~60 regs
// total -> 3 CTAs/SM. Per edge-half: 8 broadcast LDS.128 + 16 fma2 + STG.64.
// ---------------------------------------------------------------------------
__global__ void __launch_bounds__(256, 3)
outmm_kernel(const float* __restrict__ bBase,
             const float* __restrict__ A_w, const float* __restrict__ A_c,
             float* __restrict__ out, int E, int nbHalf) {
    __shared__ __align__(16) ull bsm[8][2][4][20];  // [warp][buf][edge][16+pad]

    const bool isW = (int)blockIdx.x < nbHalf;
    const int bid = isW ? blockIdx.x : blockIdx.x - nbHalf;
    const float* A = isW ? A_w : A_c;
    const float* bIn = bBase + (isW ? 0 : (size_t)E * 16);
    float* o = isW ? out : out + (size_t)E * 128;

    const int lane = threadIdx.x & 31;
    const int w = threadIdx.x >> 5;
    const int colHalf = w & 1;

    // A -> regs: lane owns cols colHalf*64 + 2*lane .. +1, all 16 k.
    ull aR[16];
    #pragma unroll
    for (int k = 0; k < 16; k++) {
        float2 v = reinterpret_cast<const float2*>(A)[k * 64 + colHalf * 32 + lane];
        aR[k] = pk2(v.x, v.y);
    }

    const int pairId = bid * 4 + (w >> 1);
    const int stepE = nbHalf * 4 * 4;        // 4 warp-pairs/block, 4 edges each
    const int el = lane >> 3, kp = lane & 7;

    int e0 = pairId * 4;
    if (e0 >= E) return;

    // prologue: 32 lanes read 4 edges x 16 floats = 256B coalesced
    float2 bv = *reinterpret_cast<const float2*>(&bIn[(size_t)e0 * 16 + 2 * lane]);
    int buf = 0;

    for (; e0 < E; e0 += stepE) {
        bsm[w][buf][el][2 * kp]     = pk2(bv.x, bv.x);
        bsm[w][buf][el][2 * kp + 1] = pk2(bv.y, bv.y);
        __syncwarp();

        // prefetch next tile's b under the FMA burst
        int en = e0 + stepE;
        en = (en < E) ? en : e0;
        bv = *reinterpret_cast<const float2*>(&bIn[(size_t)en * 16 + 2 * lane]);

        #pragma unroll
        for (int e = 0; e < 4; e++) {
            ull acc = 0ull;
            #pragma unroll
            for (int k2 = 0; k2 < 8; k2++) {
                ulonglong2 q =
                    *reinterpret_cast<const ulonglong2*>(&bsm[w][buf][e][2 * k2]);
                fma2(acc, q.x, aR[2 * k2]);
                fma2(acc, q.y, aR[2 * k2 + 1]);
            }
            float x, y;
            upk(acc, x, y);
            *reinterpret_cast<float2*>(
                o + (size_t)(e0 + e) * 128 + colHalf * 64 + 2 * lane) =
                make_float2(x, y);
        }
        buf ^= 1;
    }
}

// ---------------------------------------------------------------------------
extern "C" void kernel_launch(void* const* d_in, const int* in_sizes, int n_in,
                              void* d_out, int out_size) {
    const float* x_paper   = (const float*)d_in[0];
    const float* x_author  = (const float*)d_in[1];
    const float* Wp_paper  = (const float*)d_in[2];
    const float* bp_paper  = (const float*)d_in[3];
    const float* Wp_author = (const float*)d_in[4];
    const float* bp_author = (const float*)d_in[5];
    const float* Ws_writes = (const float*)d_in[6];
    const float* bs_writes = (const float*)d_in[7];
    const float* A_writes  = (const float*)d_in[8];
    const float* Ws_cites  = (const float*)d_in[9];
    const float* bs_cites  = (const float*)d_in[10];
    const float* A_cites   = (const float*)d_in[11];
    const int*   ei_writes = (const int*)d_in[12];
    const int*   ei_cites  = (const int*)d_in[13];
    float* out = (float*)d_out;

    const int Np = in_sizes[0] / 256;
    const int Na = in_sizes[1] / 128;
    const int E  = in_sizes[12] / 2;

    float *Mp, *cp, *Ma, *ca, *pL, *aL, *bT;
    cudaGetSymbolAddress((void**)&Mp, g_Mp);
    cudaGetSymbolAddress((void**)&cp, g_cp);
    cudaGetSymbolAddress((void**)&Ma, g_Ma);
    cudaGetSymbolAddress((void**)&ca, g_ca);
    cudaGetSymbolAddress((void**)&pL, g_paperL);
    cudaGetSymbolAddress((void**)&aL, g_authorL);
    cudaGetSymbolAddress((void**)&bT, g_b);

    cudaMemsetAsync(Mp, 0, 48 * 256 * sizeof(float));
    cudaMemsetAsync(cp, 0, 48 * sizeof(float));
    cudaMemsetAsync(Ma, 0, 16 * 128 * sizeof(float));
    cudaMemsetAsync(ca, 0, 16 * sizeof(float));

    fold_kernel<<<dim3(64, 4), 256>>>(Wp_paper, bp_paper, Wp_author, bp_author,
                                      Ws_writes, bs_writes, Ws_cites, bs_cites);

    const int npB = (Np + 127) / 128;
    const int naB = (Na + 127) / 128;
    node_kernel<<<npB + naB, 256>>>(x_paper, x_author, Mp, cp, Ma, ca,
                                    pL, aL, Np, Na, npB);

    const int nbA = 592;   // softmax: 4 CTAs/SM, high occupancy
    softmax_kernel<<<2 * nbA, 256>>>(ei_writes, ei_cites, E, aL, pL, bT, nbA);

    const int nbB = 222;   // matmul: 3 CTAs/SM x 148 SMs / 2 edge types
    outmm_kernel<<<2 * nbB, 256>>>(bT, A_writes, A_cites, out, E, nbB);
}

// round 7
// speedup vs baseline: 1.1677x; 1.1677x over previous
#include <cuda_runtime.h>
#include <cuda_bf16.h>
#include <cstdint>

// ---------------------------------------------------------------------------
// HeteroEdgePromptPlus — folded formulation.
//   logits[e,k] = srcLogits[src(e),k] + dstLogits[dst(e),k]   (bias folded)
//   b = softmax(leaky_relu(logits)) ; out[e] = b @ A
// Single fused edge kernel: half-warp softmax -> smem {b,b} -> A-in-regs MM.
// ---------------------------------------------------------------------------

#define MAXN 50000
typedef unsigned long long ull;

__device__ float g_Mp[48 * 256];
__device__ float g_cp[48];
__device__ float g_Ma[16 * 128];
__device__ float g_ca[16];
__device__ float g_paperL[(size_t)MAXN * 48];
__device__ float g_authorL[(size_t)MAXN * 16];

// ---- f32x2 packed helpers (Blackwell) -------------------------------------
__device__ __forceinline__ ull pk2(float x, float y) {
    ull r;
    asm("mov.b64 %0, {%1, %2};" : "=l"(r) : "f"(x), "f"(y));
    return r;
}
__device__ __forceinline__ void upk(ull v, float& x, float& y) {
    asm("mov.b64 {%0, %1}, %2;" : "=f"(x), "=f"(y) : "l"(v));
}
__device__ __forceinline__ void fma2(ull& d, ull a, ull b) {
    asm("fma.rn.f32x2 %0, %1, %2, %0;" : "+l"(d) : "l"(a), "l"(b));
}
__device__ __forceinline__ void st4(float* p, ull a, ull b) {
    float x, y, z, w;
    upk(a, x, y);
    upk(b, z, w);
    *reinterpret_cast<float4*>(p) = make_float4(x, y, z, w);
}

// ---------------------------------------------------------------------------
// Kernel 1: fold weights. grid = (64, 4): x = output row, y = p-chunk of 32.
// ---------------------------------------------------------------------------
__global__ void fold_kernel(const float* __restrict__ Wp_p,
                            const float* __restrict__ bp_p,
                            const float* __restrict__ Wp_a,
                            const float* __restrict__ bp_a,
                            const float* __restrict__ Ws_w,
                            const float* __restrict__ bs_w,
                            const float* __restrict__ Ws_c,
                            const float* __restrict__ bs_c) {
    const int b = blockIdx.x, t = threadIdx.x;
    const int pBeg = blockIdx.y * 32, pEnd = pBeg + 32;
    if (b < 48) {
        int k = b & 15, grp = b >> 4;
        const float* wrow = (grp == 0) ? (Ws_w + k * 256 + 128)
                          : (grp == 1) ? (Ws_c + k * 256)
                                       : (Ws_c + k * 256 + 128);
        float a0 = 0.f, a1 = 0.f, a2 = 0.f, a3 = 0.f;
        #pragma unroll
        for (int p = pBeg; p < pEnd; p += 4) {
            a0 = fmaf(__ldg(&wrow[p + 0]), __ldg(&Wp_p[(p + 0) * 256 + t]), a0);
            a1 = fmaf(__ldg(&wrow[p + 1]), __ldg(&Wp_p[(p + 1) * 256 + t]), a1);
            a2 = fmaf(__ldg(&wrow[p + 2]), __ldg(&Wp_p[(p + 2) * 256 + t]), a2);
            a3 = fmaf(__ldg(&wrow[p + 3]), __ldg(&Wp_p[(p + 3) * 256 + t]), a3);
        }
        atomicAdd(&g_Mp[b * 256 + t], (a0 + a1) + (a2 + a3));
        if (t == 0) {
            float c0 = (blockIdx.y == 0)
                           ? ((grp == 0) ? bs_w[k] : (grp == 2) ? bs_c[k] : 0.f)
                           : 0.f;
            float c1 = 0.f, c2 = 0.f, c3 = 0.f;
            #pragma unroll
            for (int p = pBeg; p < pEnd; p += 4) {
                c0 = fmaf(wrow[p + 0], bp_p[p + 0], c0);
                c1 = fmaf(wrow[p + 1], bp_p[p + 1], c1);
                c2 = fmaf(wrow[p + 2], bp_p[p + 2], c2);
                c3 = fmaf(wrow[p + 3], bp_p[p + 3], c3);
            }
            atomicAdd(&g_cp[b], (c0 + c1) + (c2 + c3));
        }
    } else {
        int k = b - 48;
        if (t < 128) {
            const float* wrow = Ws_w + k * 256;  // src half -> author
            float a0 = 0.f, a1 = 0.f, a2 = 0.f, a3 = 0.f;
            #pragma unroll
            for (int p = pBeg; p < pEnd; p += 4) {
                a0 = fmaf(__ldg(&wrow[p + 0]), __ldg(&Wp_a[(p + 0) * 128 + t]), a0);
                a1 = fmaf(__ldg(&wrow[p + 1]), __ldg(&Wp_a[(p + 1) * 128 + t]), a1);
                a2 = fmaf(__ldg(&wrow[p + 2]), __ldg(&Wp_a[(p + 2) * 128 + t]), a2);
                a3 = fmaf(__ldg(&wrow[p + 3]), __ldg(&Wp_a[(p + 3) * 128 + t]), a3);
            }
            atomicAdd(&g_Ma[k * 128 + t], (a0 + a1) + (a2 + a3));
            if (t == 0) {
                float c0 = 0.f, c1 = 0.f, c2 = 0.f, c3 = 0.f;
                #pragma unroll
                for (int p = pBeg; p < pEnd; p += 4) {
                    c0 = fmaf(wrow[p + 0], bp_a[p + 0], c0);
                    c1 = fmaf(wrow[p + 1], bp_a[p + 1], c1);
                    c2 = fmaf(wrow[p + 2], bp_a[p + 2], c2);
                    c3 = fmaf(wrow[p + 3], bp_a[p + 3], c3);
                }
                atomicAdd(&g_ca[k], (c0 + c1) + (c2 + c3));
            }
        }
    }
}

// ---------------------------------------------------------------------------
// Kernel 2: node logits  out[N,KOUT] = X[N,KDIM] @ M[KOUT,KDIM].T + c
// ---------------------------------------------------------------------------
template <int KDIM, int KOUT, int OPT>
__device__ __forceinline__ void node_body(const float* __restrict__ X,
                                          const float* __restrict__ M,
                                          const float* __restrict__ c,
                                          float* __restrict__ out, int N,
                                          int blk, float* Xs, float* Ms) {
    constexpr int KT = 32;
    const int t = threadIdx.x;
    const int n0 = blk * 128;
    const int ng = t & 63;
    const int og = t >> 6;

    ull acc0[OPT / 2], acc1[OPT / 2];
    #pragma unroll
    for (int i = 0; i < OPT / 2; i++) { acc0[i] = 0ull; acc1[i] = 0ull; }

    const int sn = n0 + (t >> 1);
    const int sj = (t & 1) * 16;
    const bool vs = sn < N;
    const float* xrow = X + (size_t)(vs ? sn : (N - 1)) * KDIM;

    for (int j0 = 0; j0 < KDIM; j0 += KT) {
        #pragma unroll
        for (int q = 0; q < 4; q++) {
            float4 v = vs ? *reinterpret_cast<const float4*>(xrow + j0 + sj + 4 * q)
                          : make_float4(0.f, 0.f, 0.f, 0.f);
            int jj = sj + 4 * q;
            Xs[(jj + 0) * 128 + (t >> 1)] = v.x;
            Xs[(jj + 1) * 128 + (t >> 1)] = v.y;
            Xs[(jj + 2) * 128 + (t >> 1)] = v.z;
            Xs[(jj + 3) * 128 + (t >> 1)] = v.w;
        }
        #pragma unroll
        for (int idx = t; idx < KT * KOUT; idx += 256) {
            int j = idx / KOUT, k = idx - j * KOUT;
            Ms[j * KOUT + k] = M[k * KDIM + j0 + j];
        }
        __syncthreads();
        #pragma unroll
        for (int j = 0; j < KT; j++) {
            float2 xv = *reinterpret_cast<const float2*>(&Xs[j * 128 + 2 * ng]);
            ull xx = pk2(xv.x, xv.x);
            ull yy = pk2(xv.y, xv.y);
            #pragma unroll
            for (int cp = 0; cp < OPT / 2; cp++) {
                ull m2 = *reinterpret_cast<const ull*>(&Ms[j * KOUT + og * OPT + 2 * cp]);
                fma2(acc0[cp], xx, m2);
                fma2(acc1[cp], yy, m2);
            }
        }
        __syncthreads();
    }

    float r0[OPT], r1[OPT];
    #pragma unroll
    for (int cp = 0; cp < OPT / 2; cp++) {
        upk(acc0[cp], r0[2 * cp], r0[2 * cp + 1]);
        upk(acc1[cp], r1[2 * cp], r1[2 * cp + 1]);
    }
    #pragma unroll
    for (int cc = 0; cc < OPT; cc++) {
        float bias = __ldg(&c[og * OPT + cc]);
        r0[cc] += bias;
        r1[cc] += bias;
    }
    const int nA = n0 + 2 * ng, nB = nA + 1;
    if (nA < N) {
        #pragma unroll
        for (int v = 0; v < OPT / 4; v++)
            *reinterpret_cast<float4*>(&out[(size_t)nA * KOUT + og * OPT + 4 * v]) =
                make_float4(r0[4 * v], r0[4 * v + 1], r0[4 * v + 2], r0[4 * v + 3]);
    }
    if (nB < N) {
        #pragma unroll
        for (int v = 0; v < OPT / 4; v++)
            *reinterpret_cast<float4*>(&out[(size_t)nB * KOUT + og * OPT + 4 * v]) =
                make_float4(r1[4 * v], r1[4 * v + 1], r1[4 * v + 2], r1[4 * v + 3]);
    }
}

__global__ void __launch_bounds__(256)
node_kernel(const float* __restrict__ xp, const float* __restrict__ xa,
            const float* __restrict__ Mp, const float* __restrict__ cp,
            const float* __restrict__ Ma, const float* __restrict__ ca,
            float* __restrict__ pL, float* __restrict__ aL,
            int Np, int Na, int npBlocks) {
    __shared__ float Xs[32 * 128];
    __shared__ float Ms[32 * 48];
    if ((int)blockIdx.x < npBlocks)
        node_body<256, 48, 12>(xp, Mp, cp, pL, Np, blockIdx.x, Xs, Ms);
    else
        node_body<128, 16, 4>(xa, Ma, ca, aL, Na, blockIdx.x - npBlocks, Xs, Ms);
}

// ---------------------------------------------------------------------------
// Kernel 3 (fused, merged edge types): round-5 matmul structure (A in regs,
// 4 cols/lane, broadcast LDS, STG.128, (256,2) = no forced spills) with the
// softmax producer inlined: half-warp softmax for 4 edges/iter, next iter's
// gathers prefetched under the 128-fma2 burst.
// ---------------------------------------------------------------------------
__global__ void __launch_bounds__(256, 2)
edge_fused_kernel(const int* __restrict__ eiW, const int* __restrict__ eiC,
                  int E,
                  const float* __restrict__ aL, const float* __restrict__ pL,
                  const float* __restrict__ A_w, const float* __restrict__ A_c,
                  float* __restrict__ out, int nbHalf) {
    __shared__ __align__(16) float2 bsh[8][2][32];

    const bool isW = (int)blockIdx.x < nbHalf;
    const int bid = isW ? blockIdx.x : blockIdx.x - nbHalf;
    const int* ei = isW ? eiW : eiC;
    const float* srcL = isW ? aL : (pL + 16);
    const int sStride = isW ? 16 : 48;
    const float* dstL = isW ? pL : (pL + 32);
    const float* A = isW ? A_w : A_c;
    float* o = isW ? out : out + (size_t)E * 128;

    const int lane = threadIdx.x & 31;
    const int w = threadIdx.x >> 5;
    const int k16 = lane & 15;
    const int half = lane >> 4;

    // A preload: lane owns output columns [4*lane, 4*lane+4) for all 16 k.
    ull aLr[16], aHr[16];
    #pragma unroll
    for (int k = 0; k < 16; k++) {
        float4 v = reinterpret_cast<const float4*>(A)[k * 32 + lane];
        aLr[k] = pk2(v.x, v.y);
        aHr[k] = pk2(v.z, v.w);
    }

    const int pairs = E >> 1;              // E even
    const int gw = bid * 8 + w;
    const int step = nbHalf * 8 * 2;       // pairs consumed per iter, all warps

    int p0 = gw * 2;
    if (p0 >= pairs) return;

    // prologue: gather + leaky-relu logits for first batch (2 pairs = 4 edges)
    float lg0, lg1;
    {
        int e0 = 2 * p0 + half, e1 = 2 * p0 + 2 + half;
        int s0 = __ldg(&ei[e0]), d0 = __ldg(&ei[E + e0]);
        int s1 = __ldg(&ei[e1]), d1 = __ldg(&ei[E + e1]);
        float l0 = __ldg(&srcL[(size_t)s0 * sStride + k16]) +
                   __ldg(&dstL[(size_t)d0 * 48 + k16]);
        float l1 = __ldg(&srcL[(size_t)s1 * sStride + k16]) +
                   __ldg(&dstL[(size_t)d1 * 48 + k16]);
        lg0 = fmaxf(l0, 0.01f * l0);
        lg1 = fmaxf(l1, 0.01f * l1);
    }

    for (; p0 < pairs; p0 += step) {
        // softmax (no max-subtraction: logits bounded, fp32 headroom is huge)
        float ex0 = __expf(lg0), ex1 = __expf(lg1);
        float s0 = ex0, s1 = ex1;
        #pragma unroll
        for (int m = 8; m; m >>= 1) {
            s0 += __shfl_xor_sync(0xffffffffu, s0, m, 16);
            s1 += __shfl_xor_sync(0xffffffffu, s1, m, 16);
        }
        float b0 = __fdividef(ex0, s0);
        float b1 = __fdividef(ex1, s1);
        bsh[w][0][lane] = make_float2(b0, b0);
        bsh[w][1][lane] = make_float2(b1, b1);

        // prefetch next batch's gathers (fly under the FMA burst below)
        float lgN0, lgN1;
        {
            int pn = min(p0 + step, pairs - 2);
            int e0 = 2 * pn + half, e1 = 2 * pn + 2 + half;
            int sa = __ldg(&ei[e0]), da = __ldg(&ei[E + e0]);
            int sb = __ldg(&ei[e1]), db = __ldg(&ei[E + e1]);
            float l0 = __ldg(&srcL[(size_t)sa * sStride + k16]) +
                       __ldg(&dstL[(size_t)da * 48 + k16]);
            float l1 = __ldg(&srcL[(size_t)sb * sStride + k16]) +
                       __ldg(&dstL[(size_t)db * 48 + k16]);
            lgN0 = fmaxf(l0, 0.01f * l0);
            lgN1 = fmaxf(l1, 0.01f * l1);
        }
        __syncwarp();

        // matmul epilogue: 4 edges x (8 broadcast LDS.128 + 32 fma2 + STG.128)
        #pragma unroll
        for (int u = 0; u < 2; u++) {
            #pragma unroll
            for (int h = 0; h < 2; h++) {
                const ulonglong2* bq =
                    reinterpret_cast<const ulonglong2*>(&bsh[w][u][16 * h]);
                ull accL = 0ull, accH = 0ull;
                #pragma unroll
                for (int k2 = 0; k2 < 8; k2++) {
                    ulonglong2 q = bq[k2];
                    fma2(accL, q.x, aLr[2 * k2]);
                    fma2(accH, q.x, aHr[2 * k2]);
                    fma2(accL, q.y, aLr[2 * k2 + 1]);
                    fma2(accH, q.y, aHr[2 * k2 + 1]);
                }
                st4(o + (size_t)(2 * (p0 + u) + h) * 128 + 4 * lane, accL, accH);
            }
        }
        __syncwarp();
        lg0 = lgN0;
        lg1 = lgN1;
    }
}

// ---------------------------------------------------------------------------
extern "C" void kernel_launch(void* const* d_in, const int* in_sizes, int n_in,
                              void* d_out, int out_size) {
    const float* x_paper   = (const float*)d_in[0];
    const float* x_author  = (const float*)d_in[1];
    const float* Wp_paper  = (const float*)d_in[2];
    const float* bp_paper  = (const float*)d_in[3];
    const float* Wp_author = (const float*)d_in[4];
    const float* bp_author = (const float*)d_in[5];
    const float* Ws_writes = (const float*)d_in[6];
    const float* bs_writes = (const float*)d_in[7];
    const float* A_writes  = (const float*)d_in[8];
    const float* Ws_cites  = (const float*)d_in[9];
    const float* bs_cites  = (const float*)d_in[10];
    const float* A_cites   = (const float*)d_in[11];
    const int*   ei_writes = (const int*)d_in[12];
    const int*   ei_cites  = (const int*)d_in[13];
    float* out = (float*)d_out;

    const int Np = in_sizes[0] / 256;
    const int Na = in_sizes[1] / 128;
    const int E  = in_sizes[12] / 2;

    float *Mp, *cp, *Ma, *ca, *pL, *aL;
    cudaGetSymbolAddress((void**)&Mp, g_Mp);
    cudaGetSymbolAddress((void**)&cp, g_cp);
    cudaGetSymbolAddress((void**)&Ma, g_Ma);
    cudaGetSymbolAddress((void**)&ca, g_ca);
    cudaGetSymbolAddress((void**)&pL, g_paperL);
    cudaGetSymbolAddress((void**)&aL, g_authorL);

    cudaMemsetAsync(Mp, 0, 48 * 256 * sizeof(float));
    cudaMemsetAsync(cp, 0, 48 * sizeof(float));
    cudaMemsetAsync(Ma, 0, 16 * 128 * sizeof(float));
    cudaMemsetAsync(ca, 0, 16 * sizeof(float));

    fold_kernel<<<dim3(64, 4), 256>>>(Wp_paper, bp_paper, Wp_author, bp_author,
                                      Ws_writes, bs_writes, Ws_cites, bs_cites);

    const int npB = (Np + 127) / 128;
    const int naB = (Na + 127) / 128;
    node_kernel<<<npB + naB, 256>>>(x_paper, x_author, Mp, cp, Ma, ca,
                                    pL, aL, Np, Na, npB);

    const int nbHalf = 296;  // 2 CTAs/SM x 148 SMs / 2 edge types
    edge_fused_kernel<<<2 * nbHalf, 256>>>(ei_writes, ei_cites, E, aL, pL,
                                           A_writes, A_cites, out, nbHalf);
}